// round 17
// baseline (speedup 1.0000x reference)
#include <cuda_runtime.h>
#include <cstdint>

#define D 128            // DH == DX == 128
#define MAX_M 4096
#define MAX_N 262144

#define PROJ_BLOCKS 128      // 32 rows each -> 4096 rows
#define CHUNK  8             // nodes per bulk copy (8 * 512B = 4KB)
#define STAGES 2

// Scratch (no allocations allowed): proj matrix
__device__ float g_proj[MAX_M * D];

// ---------------------------------------------------------------------------
// PTX helpers: mbarrier + cp.async.bulk + f32x2
// ---------------------------------------------------------------------------
__device__ __forceinline__ uint32_t smem_u32(const void* p) {
    return (uint32_t)__cvta_generic_to_shared(p);
}
__device__ __forceinline__ void mbar_init(uint32_t bar, uint32_t cnt) {
    asm volatile("mbarrier.init.shared.b64 [%0], %1;" :: "r"(bar), "r"(cnt) : "memory");
}
__device__ __forceinline__ void mbar_expect(uint32_t bar, uint32_t bytes) {
    asm volatile("mbarrier.arrive.expect_tx.shared.b64 _, [%0], %1;"
                 :: "r"(bar), "r"(bytes) : "memory");
}
__device__ __forceinline__ void bulk_ld(uint32_t dst, const void* src,
                                        uint32_t bytes, uint32_t bar) {
    asm volatile(
        "cp.async.bulk.shared::cta.global.mbarrier::complete_tx::bytes [%0], [%1], %2, [%3];"
        :: "r"(dst), "l"(src), "r"(bytes), "r"(bar) : "memory");
}
__device__ __forceinline__ void mbar_wait(uint32_t bar, uint32_t phase) {
    uint32_t done;
    asm volatile(
        "{\n\t.reg .pred p;\n\t"
        "mbarrier.try_wait.parity.acquire.cta.shared::cta.b64 p, [%1], %2;\n\t"
        "selp.b32 %0, 1, 0, p;\n\t}"
        : "=r"(done) : "r"(bar), "r"(phase) : "memory");
    if (!done) {
        asm volatile(
            "{\n\t.reg .pred P1;\n\t"
            "WAIT_LOOP_%=:\n\t"
            "mbarrier.try_wait.parity.acquire.cta.shared::cta.b64 P1, [%0], %1, 0x989680;\n\t"
            "@P1 bra.uni WAIT_DONE_%=;\n\t"
            "bra.uni WAIT_LOOP_%=;\n\t"
            "WAIT_DONE_%=:\n\t}"
            :: "r"(bar), "r"(phase) : "memory");
    }
}
__device__ __forceinline__ unsigned long long pack2(float lo, float hi) {
    unsigned long long r;
    asm("mov.b64 %0, {%1, %2};" : "=l"(r) : "f"(lo), "f"(hi));
    return r;
}
__device__ __forceinline__ void fma2(unsigned long long& d,
                                     unsigned long long a,
                                     unsigned long long b) {
    asm("fma.rn.f32x2 %0, %1, %2, %0;" : "+l"(d) : "l"(a), "l"(b));
}

// ---------------------------------------------------------------------------
// Kernel A: proj = h @ a ONLY (offsets pass eliminated — boundaries are now
// binary-searched inside attn, overlapped with this kernel via PDL).
// Packed f32x2 FFMA, 128 fat blocks x 32 rows, PDL trigger at entry.
// ---------------------------------------------------------------------------
__global__ __launch_bounds__(256) void pre_kernel(const float* __restrict__ h,
                                                  const float* __restrict__ a,
                                                  int m) {
    cudaTriggerProgrammaticLaunchCompletion();
    extern __shared__ unsigned char dyn[];
    int tid = threadIdx.x;

    float4* a_sh4 = (float4*)dyn;              // 64 KB: all of a
    float4* h_sh4 = (float4*)(dyn + 65536);    // 16 KB: 32 h rows
    const ulonglong2* a_shp = (const ulonglong2*)dyn;  // aliased pair view

    int cg = tid & 31;    // cols cg*4..cg*4+3
    int rg = tid >> 5;    // rows rg*4..rg*4+3
    int rowBase = blockIdx.x * 32;

    const float4* h4 = (const float4*)h;
    const float4* a4 = (const float4*)a;

#pragma unroll
    for (int i = 0; i < 16; i++)
        a_sh4[tid + i * 256] = a4[tid + i * 256];
#pragma unroll
    for (int i = 0; i < 4; i++)
        h_sh4[tid + i * 256] = h4[rowBase * 32 + tid + i * 256];
    __syncthreads();

    unsigned long long acc01[4], acc23[4];
#pragma unroll
    for (int r = 0; r < 4; r++) { acc01[r] = 0ull; acc23[r] = 0ull; }

#pragma unroll 4
    for (int k4 = 0; k4 < 32; k4++) {
        ulonglong2 av0 = a_shp[(k4 * 4 + 0) * 32 + cg];
        ulonglong2 av1 = a_shp[(k4 * 4 + 1) * 32 + cg];
        ulonglong2 av2 = a_shp[(k4 * 4 + 2) * 32 + cg];
        ulonglong2 av3 = a_shp[(k4 * 4 + 3) * 32 + cg];
#pragma unroll
        for (int r = 0; r < 4; r++) {
            float4 hq = h_sh4[(rg * 4 + r) * 32 + k4];  // warp-uniform
            unsigned long long h0 = pack2(hq.x, hq.x);
            unsigned long long h1 = pack2(hq.y, hq.y);
            unsigned long long h2 = pack2(hq.z, hq.z);
            unsigned long long h3 = pack2(hq.w, hq.w);
            fma2(acc01[r], h0, av0.x); fma2(acc23[r], h0, av0.y);
            fma2(acc01[r], h1, av1.x); fma2(acc23[r], h1, av1.y);
            fma2(acc01[r], h2, av2.x); fma2(acc23[r], h2, av2.y);
            fma2(acc01[r], h3, av3.x); fma2(acc23[r], h3, av3.y);
        }
    }

    ulonglong2* p2 = (ulonglong2*)g_proj;
#pragma unroll
    for (int r = 0; r < 4; r++) {
        int row = rowBase + rg * 4 + r;
        p2[row * 32 + cg] = make_ulonglong2(acc01[r], acc23[r]);
    }
}

// ---------------------------------------------------------------------------
// Flash helpers (R12 versions — best measured)
// ---------------------------------------------------------------------------
__device__ __forceinline__ float warp_dot(float4 v, float4 p) {
    float d = fmaf(v.x, p.x, fmaf(v.y, p.y, fmaf(v.z, p.z, v.w * p.w)));
    d += __shfl_xor_sync(0xffffffffu, d, 16);
    d += __shfl_xor_sync(0xffffffffu, d, 8);
    d += __shfl_xor_sync(0xffffffffu, d, 4);
    d += __shfl_xor_sync(0xffffffffu, d, 2);
    d += __shfl_xor_sync(0xffffffffu, d, 1);
    return d;
}

__device__ __forceinline__ void flash4(const float4* __restrict__ b, float4 p,
                                       float& m_w, float& z_w, float4& acc) {
    float4 v0 = b[0];
    float4 v1 = b[32];
    float4 v2 = b[64];
    float4 v3 = b[96];
    float d0 = warp_dot(v0, p);
    float d1 = warp_dot(v1, p);
    float d2 = warp_dot(v2, p);
    float d3 = warp_dot(v3, p);
    float m_new = fmaxf(fmaxf(m_w, fmaxf(d0, d1)), fmaxf(d2, d3));
    float c  = __expf(m_w - m_new);
    float e0 = __expf(d0 - m_new);
    float e1 = __expf(d1 - m_new);
    float e2 = __expf(d2 - m_new);
    float e3 = __expf(d3 - m_new);
    z_w   = fmaf(z_w, c, (e0 + e1) + (e2 + e3));
    acc.x = fmaf(acc.x, c, fmaf(e0, v0.x, fmaf(e1, v1.x, fmaf(e2, v2.x, e3 * v3.x))));
    acc.y = fmaf(acc.y, c, fmaf(e0, v0.y, fmaf(e1, v1.y, fmaf(e2, v2.y, e3 * v3.y))));
    acc.z = fmaf(acc.z, c, fmaf(e0, v0.z, fmaf(e1, v1.z, fmaf(e2, v2.z, e3 * v3.z))));
    acc.w = fmaf(acc.w, c, fmaf(e0, v0.w, fmaf(e1, v1.w, fmaf(e2, v2.w, e3 * v3.w))));
    m_w = m_new;
}

__device__ __forceinline__ void flash1(float4 v, float4 p,
                                       float& m_w, float& z_w, float4& acc) {
    float d  = warp_dot(v, p);
    float m_new = fmaxf(m_w, d);
    float c = __expf(m_w - m_new);
    float e = __expf(d - m_new);
    z_w   = fmaf(z_w, c, e);
    acc.x = fmaf(acc.x, c, e * v.x);
    acc.y = fmaf(acc.y, c, e * v.y);
    acc.z = fmaf(acc.z, c, e * v.z);
    acc.w = fmaf(acc.w, c, e * v.w);
    m_w = m_new;
}

// ---------------------------------------------------------------------------
// Kernel B: TWO WARPS PER GRAPH, bulk-async pipelined online softmax.
// Graph boundaries found by in-block binary search on sorted seg (lanes 0-2
// of warp 0, concurrent) — runs BEFORE cudaGridDependencySynchronize(), so
// it overlaps pre_kernel's execution under PDL. No g_offsets array at all.
// ---------------------------------------------------------------------------
__global__ __launch_bounds__(128) void attn_kernel(const float* __restrict__ x,
                                                   const int* __restrict__ seg,
                                                   float* __restrict__ out,
                                                   int n, int m) {
    __shared__ float4   s_buf[4][STAGES][CHUNK * 32];  // 32 KB
    __shared__ uint64_t s_bar[4][STAGES];
    __shared__ float    s_m[4];
    __shared__ float    s_z[4];
    __shared__ float4   s_accs[2][32];
    __shared__ int      s_off[3];   // boundaries of graphs 2b, 2b+1

    int tid  = threadIdx.x;
    int lane = tid & 31;
    int w    = tid >> 5;    // 0..3
    int pp   = w >> 1;      // pair 0..1
    int half = w & 1;
    int g    = blockIdx.x * 2 + pp;

    if (lane == 0) {
        mbar_init(smem_u32(&s_bar[w][0]), 1);
        mbar_init(smem_u32(&s_bar[w][1]), 1);
    }

    // ---- boundary binary searches (independent of pre_kernel; overlap) ----
    if (w == 0 && lane < 3) {
        int gq = blockIdx.x * 2 + lane;     // want first i with seg[i] >= gq
        int lo = 0, hi = n;
        while (lo < hi) {
            int mid = (lo + hi) >> 1;
            if (__ldg(&seg[mid]) < gq) lo = mid + 1; else hi = mid;
        }
        s_off[lane] = lo;
    }
    __syncthreads();

    // PDL: wait for pre_kernel's g_proj writes to be visible
    cudaGridDependencySynchronize();

    bool active = (g < m);
    int s0 = s_off[pp];
    int e0 = s_off[pp + 1];
    int cnt = e0 - s0;
    int h0  = (cnt + 1) >> 1;
    int beg = half ? (s0 + h0) : s0;
    int fin = half ? e0 : (s0 + h0);
    int len = fin - beg;
    int nfull = (len > 0) ? (len >> 3) : 0;   // full CHUNK-node chunks

    const float4* x4 = (const float4*)x;

    float4 p = make_float4(0.f, 0.f, 0.f, 0.f);
    if (active && cnt > 0)
        p = ((const float4*)g_proj)[g * 32 + lane];

    // ---- prologue: fill the pipeline ----
    if (lane == 0) {
        int npre = nfull < STAGES ? nfull : STAGES;
        for (int k = 0; k < npre; k++) {
            uint32_t bar = smem_u32(&s_bar[w][k]);
            mbar_expect(bar, CHUNK * 512u);
            bulk_ld(smem_u32(&s_buf[w][k][0]),
                    x4 + (size_t)(beg + k * CHUNK) * 32, CHUNK * 512u, bar);
        }
    }

    const float NEG_INF = -3.402823466e38f;
    float  m_w = NEG_INF;
    float  z_w = 0.f;
    float4 acc = make_float4(0.f, 0.f, 0.f, 0.f);

    // ---- main pipelined loop ----
    for (int c = 0; c < nfull; c++) {
        int st = c & 1;
        mbar_wait(smem_u32(&s_bar[w][st]), (c >> 1) & 1);
        const float4* b = &s_buf[w][st][lane];
        flash4(b,       p, m_w, z_w, acc);   // nodes 0..3
        flash4(b + 128, p, m_w, z_w, acc);   // nodes 4..7
        if (c + 2 < nfull && lane == 0) {
            uint32_t bar = smem_u32(&s_bar[w][st]);
            mbar_expect(bar, CHUNK * 512u);
            bulk_ld(smem_u32(&s_buf[w][st][0]),
                    x4 + (size_t)(beg + (c + 2) * CHUNK) * 32, CHUNK * 512u, bar);
        }
    }

    // ---- remainder nodes (<CHUNK) via direct LDG ----
    for (int i = beg + nfull * CHUNK; i < fin; ++i)
        flash1(x4[(size_t)i * 32 + lane], p, m_w, z_w, acc);

    // ---- pair combine ----
    if (lane == 0) { s_m[w] = m_w; s_z[w] = z_w; }
    if (half) s_accs[pp][lane] = acc;
    __syncthreads();

    if (!half && active) {
        float4* out4 = (float4*)out;
        if (cnt <= 0) {
            out4[g * 32 + lane] = make_float4(0.f, 0.f, 0.f, 0.f);
        } else {
            float  m1 = s_m[w + 1];
            float  z1 = s_z[w + 1];
            float4 a1 = s_accs[pp][lane];
            float mg = fmaxf(m_w, m1);       // finite: half0 non-empty
            float f0 = __expf(m_w - mg);
            float f1 = __expf(m1 - mg);      // 0 if half1 empty
            float z  = fmaf(z_w, f0, z1 * f1);
            float inv = 1.f / z;
            out4[g * 32 + lane] = make_float4(
                fmaf(acc.x, f0, a1.x * f1) * inv,
                fmaf(acc.y, f0, a1.y * f1) * inv,
                fmaf(acc.z, f0, a1.z * f1) * inv,
                fmaf(acc.w, f0, a1.w * f1) * inv);
        }
    }
}

// ---------------------------------------------------------------------------
// Launch: inputs per metadata order: h (M*128 f32), x (N*128 f32),
// a (128*128 f32), segment_ids (N int32). Output: M*128 f32.
// attn launched with PDL so its front-end (mbar init + boundary searches)
// overlaps pre_kernel's proj computation.
// ---------------------------------------------------------------------------
extern "C" void kernel_launch(void* const* d_in, const int* in_sizes, int n_in,
                              void* d_out, int out_size) {
    const float* h   = (const float*)d_in[0];
    const float* x   = (const float*)d_in[1];
    const float* a   = (const float*)d_in[2];
    const int*   seg = (const int*)d_in[3];
    float* out = (float*)d_out;

    int m = in_sizes[0] / D;   // 4096
    int n = in_sizes[3];       // 262144

    int pre_smem = 65536 + 16384;   // a (64KB) + h tile (16KB)
    static bool attr_set = false;
    if (!attr_set) {
        cudaFuncSetAttribute(pre_kernel,
                             cudaFuncAttributeMaxDynamicSharedMemorySize,
                             pre_smem);
        attr_set = true;
    }

    pre_kernel<<<PROJ_BLOCKS, 256, pre_smem>>>(h, a, m);

    cudaLaunchConfig_t cfg = {};
    cfg.gridDim  = dim3((unsigned)((m + 1) / 2), 1, 1);
    cfg.blockDim = dim3(128, 1, 1);
    cudaLaunchAttribute attrs[1];
    attrs[0].id = cudaLaunchAttributeProgrammaticStreamSerialization;
    attrs[0].val.programmaticStreamSerializationAllowed = 1;
    cfg.attrs = attrs;
    cfg.numAttrs = 1;
    cudaLaunchKernelEx(&cfg, attn_kernel, x, seg, out, n, m);
}